// round 1
// baseline (speedup 1.0000x reference)
#include <cuda_runtime.h>
#include <cuda_bf16.h>
#include <cstdint>

// Problem dims (fixed by the dataset)
#define BATCH 64
#define TT    512
#define DD    512
#define HH    1024
#define MM    (BATCH * TT)        // 32768 rows
#define KK    DD                  // 512
#define NN    HH                  // 1024

// Scratch: projections xz, xr, xh, each [M, N] fp32.
// 3 * 32768 * 1024 * 4 B = 402,653,184 B. __device__ global (no runtime alloc).
__device__ float g_proj[3ULL * MM * NN];

// ---------------------------------------------------------------------------
// GEMM: C[w] = X @ K[w],  X:[M,K] row-major, K:[K,N] row-major, C:[M,N]
// 128x128 block tile, BK=16, 256 threads, 8x8 per-thread microtile, fp32.
// ---------------------------------------------------------------------------
#define BM 128
#define BN 128
#define BK 16

__global__ __launch_bounds__(256, 2) void gemm3_kernel(
    const float* __restrict__ X,
    const float* __restrict__ Kz,
    const float* __restrict__ Kr,
    const float* __restrict__ Kh)
{
    const float* Bp = (blockIdx.z == 0) ? Kz : (blockIdx.z == 1) ? Kr : Kh;
    float* Cp = g_proj + (size_t)blockIdx.z * (size_t)MM * NN;

    __shared__ float As[BK][BM + 4];
    __shared__ float Bs[BK][BN + 4];

    const int tid = threadIdx.x;           // 0..255
    const int bm  = blockIdx.y * BM;
    const int bn  = blockIdx.x * BN;
    const int tr  = tid >> 4;               // 0..15 (row group)
    const int tc  = tid & 15;               // 0..15 (col group)

    float acc[8][8];
#pragma unroll
    for (int i = 0; i < 8; i++)
#pragma unroll
        for (int j = 0; j < 8; j++) acc[i][j] = 0.0f;

    for (int k0 = 0; k0 < KK; k0 += BK) {
        // Load A tile: 128 rows x 16 cols = 512 float4, 2 per thread.
        // Load B tile: 16 rows x 128 cols = 512 float4, 2 per thread.
#pragma unroll
        for (int i = 0; i < 2; i++) {
            int f = tid + i * 256;
            // A: row = f/4 (0..127), k-offset = (f%4)*4
            int ar  = f >> 2;
            int ac4 = (f & 3) * 4;
            float4 av = *(const float4*)(X + (size_t)(bm + ar) * KK + k0 + ac4);
            As[ac4 + 0][ar] = av.x;
            As[ac4 + 1][ar] = av.y;
            As[ac4 + 2][ar] = av.z;
            As[ac4 + 3][ar] = av.w;
            // B: row k = f/32 (0..15), n-offset = (f%32)*4
            int brw = f >> 5;
            int bc4 = (f & 31) * 4;
            float4 bv = *(const float4*)(Bp + (size_t)(k0 + brw) * NN + bn + bc4);
            *(float4*)&Bs[brw][bc4] = bv;   // row stride (BN+4)*4 = 528 B, 16B-aligned
        }
        __syncthreads();

#pragma unroll
        for (int kk = 0; kk < BK; kk++) {
            float ra[8], rb[8];
            // two float4 loads each (contiguous in smem rows)
            *(float4*)&ra[0] = *(const float4*)&As[kk][tr * 8 + 0];
            *(float4*)&ra[4] = *(const float4*)&As[kk][tr * 8 + 4];
            *(float4*)&rb[0] = *(const float4*)&Bs[kk][tc * 8 + 0];
            *(float4*)&rb[4] = *(const float4*)&Bs[kk][tc * 8 + 4];
#pragma unroll
            for (int i = 0; i < 8; i++)
#pragma unroll
                for (int j = 0; j < 8; j++)
                    acc[i][j] = fmaf(ra[i], rb[j], acc[i][j]);
        }
        __syncthreads();
    }

    // Store 8x8 tile as 2 float4 per row.
#pragma unroll
    for (int i = 0; i < 8; i++) {
        float4* o = (float4*)(Cp + (size_t)(bm + tr * 8 + i) * NN + bn + tc * 8);
        o[0] = make_float4(acc[i][0], acc[i][1], acc[i][2], acc[i][3]);
        o[1] = make_float4(acc[i][4], acc[i][5], acc[i][6], acc[i][7]);
    }
}

// ---------------------------------------------------------------------------
// Recurrence scan: per-channel (b, h) independent, sequential over T.
// Each thread owns 4 adjacent h channels (float4), prefetches next timestep.
//   r = tanh(xr + h*mr + br) + 1
//   z = sigmoid(xz + h*mz + bz) = 0.5*tanh(0.5*(..)) + 0.5
//   h' = z*h + (1-z)*tanh(xh + r*h)
// ---------------------------------------------------------------------------
__device__ __forceinline__ float brc_step(float xz, float xr, float xh,
                                          float h, float mzv, float mrv,
                                          float bzv, float brv)
{
    float r = tanhf(fmaf(h, mrv, xr + brv)) + 1.0f;
    float z = 0.5f * tanhf(0.5f * fmaf(h, mzv, xz + bzv)) + 0.5f;
    float c = tanhf(fmaf(r, h, xh));
    return fmaf(z, h - c, c);   // z*h + (1-z)*c
}

__global__ __launch_bounds__(128) void scan_kernel(
    const float* __restrict__ mz,
    const float* __restrict__ mr,
    const float* __restrict__ br,
    const float* __restrict__ bz,
    float* __restrict__ out)
{
    const int ch4 = blockIdx.x * blockDim.x + threadIdx.x;   // 0 .. 16383
    const int H4  = HH / 4;
    const int b   = ch4 / H4;
    const int h   = (ch4 % H4) * 4;

    const float4 mzv = *(const float4*)(mz + h);
    const float4 mrv = *(const float4*)(mr + h);
    const float4 brv = *(const float4*)(br + h);
    const float4 bzv = *(const float4*)(bz + h);

    const size_t base = (size_t)b * TT * HH + h;
    const size_t PLANE = (size_t)MM * NN;
    const float4* pz = (const float4*)(g_proj + 0 * PLANE + base);
    const float4* pr = (const float4*)(g_proj + 1 * PLANE + base);
    const float4* ph = (const float4*)(g_proj + 2 * PLANE + base);
    float4* po = (float4*)(out + base);

    float4 hs = make_float4(0.f, 0.f, 0.f, 0.f);

    float4 xz0 = pz[0], xr0 = pr[0], xh0 = ph[0];

#pragma unroll 1
    for (int t = 0; t < TT; t++) {
        float4 xz1, xr1, xh1;
        if (t + 1 < TT) {
            size_t o = (size_t)(t + 1) * H4;
            xz1 = pz[o]; xr1 = pr[o]; xh1 = ph[o];
        }
        hs.x = brc_step(xz0.x, xr0.x, xh0.x, hs.x, mzv.x, mrv.x, bzv.x, brv.x);
        hs.y = brc_step(xz0.y, xr0.y, xh0.y, hs.y, mzv.y, mrv.y, bzv.y, brv.y);
        hs.z = brc_step(xz0.z, xr0.z, xh0.z, hs.z, mzv.z, mrv.z, bzv.z, brv.z);
        hs.w = brc_step(xz0.w, xr0.w, xh0.w, hs.w, mzv.w, mrv.w, bzv.w, brv.w);
        po[(size_t)t * H4] = hs;
        xz0 = xz1; xr0 = xr1; xh0 = xh1;
    }
}

// ---------------------------------------------------------------------------
// Launch
// Inputs (metadata order): x, kz, kr, kh, mz, mr, br, bz
// ---------------------------------------------------------------------------
extern "C" void kernel_launch(void* const* d_in, const int* in_sizes, int n_in,
                              void* d_out, int out_size)
{
    const float* x  = (const float*)d_in[0];
    const float* kz = (const float*)d_in[1];
    const float* kr = (const float*)d_in[2];
    const float* kh = (const float*)d_in[3];
    const float* mz = (const float*)d_in[4];
    const float* mr = (const float*)d_in[5];
    const float* br = (const float*)d_in[6];
    const float* bz = (const float*)d_in[7];
    float* out = (float*)d_out;

    dim3 ggrid(NN / BN, MM / BM, 3);   // (8, 256, 3)
    gemm3_kernel<<<ggrid, 256>>>(x, kz, kr, kh);

    const int nthreads = BATCH * HH / 4;   // 16384
    scan_kernel<<<nthreads / 128, 128>>>(mz, mr, br, bz, out);
}

// round 3
// speedup vs baseline: 2.0416x; 2.0416x over previous
#include <cuda_runtime.h>
#include <cuda_bf16.h>
#include <cstdint>

#define BATCH 64
#define TT    512
#define DD    512
#define HH    1024
#define MM    (BATCH * TT)        // 32768
#define KK    DD                  // 512
#define NN    HH                  // 1024

// ---------------- device scratch (no runtime alloc) ----------------
__device__ float g_proj[3ULL * MM * NN];                    // 384 MB fp32 projections
__device__ __nv_bfloat16 g_xsplit[2ULL * MM * KK];          // x hi/lo bf16
__device__ __nv_bfloat16 g_wT[3ULL * 2 * NN * KK];          // weights^T hi/lo [w][2][N][K]

__device__ __forceinline__ uint32_t smem_u32(const void* p) {
    uint32_t a;
    asm("{ .reg .u64 t; cvta.to.shared.u64 t, %1; cvt.u32.u64 %0, t; }" : "=r"(a) : "l"(p));
    return a;
}

#define CP16(sa, gp) asm volatile("cp.async.cg.shared.global [%0], [%1], 16;" :: "r"(sa), "l"(gp))
#define CP_COMMIT()  asm volatile("cp.async.commit_group;" ::: "memory")
#define CP_WAIT(n)   asm volatile("cp.async.wait_group %0;" :: "n"(n) : "memory")

__device__ __forceinline__ void ldm_x4(uint32_t a, uint32_t& r0, uint32_t& r1, uint32_t& r2, uint32_t& r3) {
    asm volatile("ldmatrix.sync.aligned.m8n8.x4.shared.b16 {%0,%1,%2,%3}, [%4];"
                 : "=r"(r0), "=r"(r1), "=r"(r2), "=r"(r3) : "r"(a));
}
__device__ __forceinline__ void mma_bf16(float* d, const uint32_t* a, const uint32_t* b) {
    asm volatile("mma.sync.aligned.m16n8k16.row.col.f32.bf16.bf16.f32 "
                 "{%0,%1,%2,%3}, {%4,%5,%6,%7}, {%8,%9}, {%0,%1,%2,%3};"
                 : "+f"(d[0]), "+f"(d[1]), "+f"(d[2]), "+f"(d[3])
                 : "r"(a[0]), "r"(a[1]), "r"(a[2]), "r"(a[3]), "r"(b[0]), "r"(b[1]));
}

// ---------------- prep: split x into bf16 hi/lo ----------------
__global__ __launch_bounds__(256) void prep_x(const float* __restrict__ x) {
    size_t i = (size_t)blockIdx.x * 256 + threadIdx.x;
    if (i >= (size_t)MM * KK / 4) return;
    float4 v = ((const float4*)x)[i];
    __nv_bfloat16 hx = __float2bfloat16_rn(v.x), hy = __float2bfloat16_rn(v.y);
    __nv_bfloat16 hz = __float2bfloat16_rn(v.z), hw = __float2bfloat16_rn(v.w);
    __nv_bfloat16 lx = __float2bfloat16_rn(v.x - __bfloat162float(hx));
    __nv_bfloat16 ly = __float2bfloat16_rn(v.y - __bfloat162float(hy));
    __nv_bfloat16 lz = __float2bfloat16_rn(v.z - __bfloat162float(hz));
    __nv_bfloat16 lw = __float2bfloat16_rn(v.w - __bfloat162float(hw));
    __nv_bfloat16* hi = g_xsplit;
    __nv_bfloat16* lo = g_xsplit + (size_t)MM * KK;
    ((__nv_bfloat162*)hi)[2 * i]     = __nv_bfloat162(hx, hy);
    ((__nv_bfloat162*)hi)[2 * i + 1] = __nv_bfloat162(hz, hw);
    ((__nv_bfloat162*)lo)[2 * i]     = __nv_bfloat162(lx, ly);
    ((__nv_bfloat162*)lo)[2 * i + 1] = __nv_bfloat162(lz, lw);
}

// ---------------- prep: transpose + split weights ----------------
__global__ __launch_bounds__(256) void prep_w(const float* __restrict__ kz,
                                              const float* __restrict__ kr,
                                              const float* __restrict__ kh) {
    size_t idx = (size_t)blockIdx.x * 256 + threadIdx.x;
    if (idx >= 3ULL * NN * KK) return;
    int w = (int)(idx / ((size_t)NN * KK));
    size_t rem = idx % ((size_t)NN * KK);
    int n = (int)(rem / KK);
    int k = (int)(rem % KK);
    const float* W = (w == 0) ? kz : (w == 1) ? kr : kh;
    float v = W[(size_t)k * NN + n];
    __nv_bfloat16 h = __float2bfloat16_rn(v);
    __nv_bfloat16 l = __float2bfloat16_rn(v - __bfloat162float(h));
    g_wT[(((size_t)w * 2 + 0) * NN + n) * KK + k] = h;
    g_wT[(((size_t)w * 2 + 1) * NN + n) * KK + k] = l;
}

// ---------------- mma.sync GEMM ----------------
// CTA 128x128, 8 warps (warp_m = wid&3 -> 32 rows, warp_n = wid>>2 -> 64 cols)
// K chunks of 32, 4-stage cp.async pipeline.
// SMEM tile: 128 rows x 32 bf16, row stride 80B (64B data + 16B pad, 16B-aligned,
// conflict-free for ldmatrix: bank(r) = 20r mod 32 distinct over 8 rows).
#define ROWB 80
#define TILE_BYTES (128 * ROWB)                  // 10240
#define STAGE_BYTES (4 * TILE_BYTES)             // Ahi, Alo, Bhi, Blo = 40960
#define NSTAGE 4
#define GEMM_SMEM (NSTAGE * STAGE_BYTES)         // 163840
#define NCHUNK (KK / 32)                         // 16

__global__ __launch_bounds__(256, 1) void gemm_mma() {
    extern __shared__ char smem[];
    const uint32_t sb = smem_u32(smem);

    const int tid = threadIdx.x;
    const int wid = tid >> 5;
    const int lid = tid & 31;
    const int bn = blockIdx.x * 128;
    const int bm = blockIdx.y * 128;
    const int w  = blockIdx.z;
    const int warp_m = wid & 3;      // 0..3 -> 32-row band
    const int warp_n = wid >> 2;     // 0..1 -> 64-col band

    const __nv_bfloat16* Ahi = g_xsplit;
    const __nv_bfloat16* Alo = g_xsplit + (size_t)MM * KK;
    const __nv_bfloat16* Bhi = g_wT + (((size_t)w * 2 + 0) * NN) * KK;
    const __nv_bfloat16* Blo = g_wT + (((size_t)w * 2 + 1) * NN) * KK;
    float* Cp = g_proj + (size_t)w * MM * NN;

    // cp.async: thread covers 2 (row, 16B-chunk) slots per tile
    const int ldr0 = tid >> 2;            // rows 0..63
    const int ldc  = (tid & 3) * 16;      // byte col 0/16/32/48
    const int ldq  = (tid & 3) * 8;       // bf16 elem col

    auto load_stage = [&](int chunk, int s) {
        const int k0 = chunk * 32;
        const uint32_t st = sb + s * STAGE_BYTES;
#pragma unroll
        for (int i = 0; i < 2; i++) {
            const int r = ldr0 + i * 64;
            const uint32_t so = (uint32_t)(r * ROWB + ldc);
            const size_t ga = (size_t)(bm + r) * KK + k0 + ldq;
            const size_t gb = (size_t)(bn + r) * KK + k0 + ldq;
            CP16(st + 0 * TILE_BYTES + so, Ahi + ga);
            CP16(st + 1 * TILE_BYTES + so, Alo + ga);
            CP16(st + 2 * TILE_BYTES + so, Bhi + gb);
            CP16(st + 3 * TILE_BYTES + so, Blo + gb);
        }
    };

    // ldmatrix lane address components
    const int a_r = (lid & 7) + ((lid >> 3) & 1) * 8;   // row within 16-row m-tile
    const int a_c = (lid >> 4) * 16;                    // byte col (k half)
    const int b_r = (lid & 7) + ((lid >> 4) ? 8 : 0);   // row within 16-row n-pair
    const int b_c = ((lid >> 3) & 1) * 16;              // byte col (k half)
    const uint32_t aRow = (uint32_t)((warp_m * 32 + a_r) * ROWB + a_c);
    const uint32_t bRow = (uint32_t)((warp_n * 64 + b_r) * ROWB + b_c);

    float acc[2][8][4];
#pragma unroll
    for (int i = 0; i < 2; i++)
#pragma unroll
        for (int j = 0; j < 8; j++)
#pragma unroll
            for (int q = 0; q < 4; q++) acc[i][j][q] = 0.0f;

    load_stage(0, 0); CP_COMMIT();
    load_stage(1, 1); CP_COMMIT();
    load_stage(2, 2); CP_COMMIT();

    for (int c = 0; c < NCHUNK; c++) {
        if (c < NCHUNK - 2)      CP_WAIT(2);
        else if (c == NCHUNK - 2) CP_WAIT(1);
        else                      CP_WAIT(0);
        __syncthreads();
        if (c + 3 < NCHUNK) { load_stage(c + 3, (c + 3) & 3); CP_COMMIT(); }

        const uint32_t st = sb + (c & 3) * STAGE_BYTES;
        const uint32_t aHiB = st + 0 * TILE_BYTES + aRow;
        const uint32_t aLoB = st + 1 * TILE_BYTES + aRow;
        const uint32_t bHiB = st + 2 * TILE_BYTES + bRow;
        const uint32_t bLoB = st + 3 * TILE_BYTES + bRow;

#pragma unroll
        for (int kq = 0; kq < 2; kq++) {                 // two k16 steps (byte offset 0 / 32)
            const uint32_t ko = kq * 32;
            uint32_t ah[2][4], al[2][4], bh[8][2], bl[8][2];
#pragma unroll
            for (int mt = 0; mt < 2; mt++) {
                ldm_x4(aHiB + mt * (16 * ROWB) + ko, ah[mt][0], ah[mt][1], ah[mt][2], ah[mt][3]);
                ldm_x4(aLoB + mt * (16 * ROWB) + ko, al[mt][0], al[mt][1], al[mt][2], al[mt][3]);
            }
#pragma unroll
            for (int np = 0; np < 4; np++) {             // pairs of n-tiles
                uint32_t r0, r1, r2, r3;
                ldm_x4(bHiB + np * (16 * ROWB) + ko, r0, r1, r2, r3);
                bh[2 * np][0] = r0; bh[2 * np][1] = r1;
                bh[2 * np + 1][0] = r2; bh[2 * np + 1][1] = r3;
                ldm_x4(bLoB + np * (16 * ROWB) + ko, r0, r1, r2, r3);
                bl[2 * np][0] = r0; bl[2 * np][1] = r1;
                bl[2 * np + 1][0] = r2; bl[2 * np + 1][1] = r3;
            }
#pragma unroll
            for (int mt = 0; mt < 2; mt++)
#pragma unroll
                for (int nt = 0; nt < 8; nt++) {
                    mma_bf16(acc[mt][nt], ah[mt], bh[nt]);
                    mma_bf16(acc[mt][nt], ah[mt], bl[nt]);
                    mma_bf16(acc[mt][nt], al[mt], bh[nt]);
                }
        }
    }

    // epilogue: direct fp32 stores (float2 per fragment half-row)
    const int er = lid >> 2;          // 0..7
    const int ec = (lid & 3) * 2;     // 0,2,4,6
#pragma unroll
    for (int mt = 0; mt < 2; mt++) {
        const int row = bm + warp_m * 32 + mt * 16 + er;
#pragma unroll
        for (int nt = 0; nt < 8; nt++) {
            const int col = bn + warp_n * 64 + nt * 8 + ec;
            float2* o0 = (float2*)(Cp + (size_t)row * NN + col);
            float2* o1 = (float2*)(Cp + (size_t)(row + 8) * NN + col);
            *o0 = make_float2(acc[mt][nt][0], acc[mt][nt][1]);
            *o1 = make_float2(acc[mt][nt][2], acc[mt][nt][3]);
        }
    }
}

// ---------------- recurrence scan (depth-4 prefetch) ----------------
__device__ __forceinline__ float brc_step(float xz, float xr, float xh,
                                          float h, float mzv, float mrv,
                                          float bzv, float brv) {
    float r = tanhf(fmaf(h, mrv, xr + brv)) + 1.0f;
    float z = 0.5f * tanhf(0.5f * fmaf(h, mzv, xz + bzv)) + 0.5f;
    float c = tanhf(fmaf(r, h, xh));
    return fmaf(z, h - c, c);
}

__global__ __launch_bounds__(128) void scan_kernel(
    const float* __restrict__ mz, const float* __restrict__ mr,
    const float* __restrict__ br, const float* __restrict__ bz,
    float* __restrict__ out) {
    const int ch4 = blockIdx.x * blockDim.x + threadIdx.x;
    const int H4 = HH / 4;
    const int b = ch4 / H4;
    const int h = (ch4 % H4) * 4;

    const float4 mzv = *(const float4*)(mz + h);
    const float4 mrv = *(const float4*)(mr + h);
    const float4 brv = *(const float4*)(br + h);
    const float4 bzv = *(const float4*)(bz + h);

    const size_t base = (size_t)b * TT * HH + h;
    const size_t PLANE = (size_t)MM * NN;
    const float4* pz = (const float4*)(g_proj + 0 * PLANE + base);
    const float4* pr = (const float4*)(g_proj + 1 * PLANE + base);
    const float4* ph = (const float4*)(g_proj + 2 * PLANE + base);
    float4* po = (float4*)(out + base);

    float4 hs = make_float4(0.f, 0.f, 0.f, 0.f);
    float4 zb[4], rb[4], hb[4];
#pragma unroll
    for (int s = 0; s < 4; s++) {
        size_t o = (size_t)s * H4;
        zb[s] = pz[o]; rb[s] = pr[o]; hb[s] = ph[o];
    }

#pragma unroll 4
    for (int t = 0; t < TT; t++) {
        const int s = t & 3;
        float4 xz0 = zb[s], xr0 = rb[s], xh0 = hb[s];
        if (t + 4 < TT) {
            size_t o = (size_t)(t + 4) * H4;
            zb[s] = pz[o]; rb[s] = pr[o]; hb[s] = ph[o];
        }
        hs.x = brc_step(xz0.x, xr0.x, xh0.x, hs.x, mzv.x, mrv.x, bzv.x, brv.x);
        hs.y = brc_step(xz0.y, xr0.y, xh0.y, hs.y, mzv.y, mrv.y, bzv.y, brv.y);
        hs.z = brc_step(xz0.z, xr0.z, xh0.z, hs.z, mzv.z, mrv.z, bzv.z, brv.z);
        hs.w = brc_step(xz0.w, xr0.w, xh0.w, hs.w, mzv.w, mrv.w, bzv.w, brv.w);
        po[(size_t)t * H4] = hs;
    }
}

// ---------------- launch ----------------
extern "C" void kernel_launch(void* const* d_in, const int* in_sizes, int n_in,
                              void* d_out, int out_size) {
    const float* x  = (const float*)d_in[0];
    const float* kz = (const float*)d_in[1];
    const float* kr = (const float*)d_in[2];
    const float* kh = (const float*)d_in[3];
    const float* mz = (const float*)d_in[4];
    const float* mr = (const float*)d_in[5];
    const float* br = (const float*)d_in[6];
    const float* bz = (const float*)d_in[7];
    float* out = (float*)d_out;

    cudaFuncSetAttribute(gemm_mma, cudaFuncAttributeMaxDynamicSharedMemorySize, GEMM_SMEM);

    prep_x<<<(MM * KK / 4 + 255) / 256, 256>>>(x);
    prep_w<<<(3 * NN * KK + 255) / 256, 256>>>(kz, kr, kh);

    dim3 ggrid(NN / 128, MM / 128, 3);   // (8, 256, 3)
    gemm_mma<<<ggrid, 256, GEMM_SMEM>>>();

    scan_kernel<<<(BATCH * HH / 4) / 128, 128>>>(mz, mr, br, bz, out);
}

// round 4
// speedup vs baseline: 4.5461x; 2.2267x over previous
#include <cuda_runtime.h>
#include <cuda_fp16.h>
#include <cstdint>

#define BATCH 64
#define TT    512
#define DD    512
#define HH    1024
#define MM    (BATCH * TT)        // 32768
#define KK    DD                  // 512
#define NN    HH                  // 1024

// ---------------- device scratch (no runtime alloc) ----------------
__device__ float g_proj[3ULL * MM * NN];       // 384 MB fp32 projections
__device__ __half g_xh[(size_t)MM * KK];       // x fp16, 32 MB
__device__ __half g_wh[3ULL * NN * KK];        // weights^T fp16 [w][N][K], 3 MB

__device__ __forceinline__ uint32_t smem_u32(const void* p) {
    uint32_t a;
    asm("{ .reg .u64 t; cvta.to.shared.u64 t, %1; cvt.u32.u64 %0, t; }" : "=r"(a) : "l"(p));
    return a;
}

#define CP16(sa, gp) asm volatile("cp.async.cg.shared.global [%0], [%1], 16;" :: "r"(sa), "l"(gp))
#define CP_COMMIT()  asm volatile("cp.async.commit_group;" ::: "memory")
#define CP_WAIT(n)   asm volatile("cp.async.wait_group %0;" :: "n"(n) : "memory")

__device__ __forceinline__ void ldm_x4(uint32_t a, uint32_t& r0, uint32_t& r1, uint32_t& r2, uint32_t& r3) {
    asm volatile("ldmatrix.sync.aligned.m8n8.x4.shared.b16 {%0,%1,%2,%3}, [%4];"
                 : "=r"(r0), "=r"(r1), "=r"(r2), "=r"(r3) : "r"(a));
}
__device__ __forceinline__ void mma_fp16(float* d, const uint32_t* a, const uint32_t* b) {
    asm volatile("mma.sync.aligned.m16n8k16.row.col.f32.f16.f16.f32 "
                 "{%0,%1,%2,%3}, {%4,%5,%6,%7}, {%8,%9}, {%0,%1,%2,%3};"
                 : "+f"(d[0]), "+f"(d[1]), "+f"(d[2]), "+f"(d[3])
                 : "r"(a[0]), "r"(a[1]), "r"(a[2]), "r"(a[3]), "r"(b[0]), "r"(b[1]));
}

// ---------------- prep: x -> fp16 ----------------
__global__ __launch_bounds__(256) void prep_x(const float* __restrict__ x) {
    size_t i = (size_t)blockIdx.x * 256 + threadIdx.x;      // per float4
    if (i >= (size_t)MM * KK / 4) return;
    float4 v = ((const float4*)x)[i];
    __half2* o = (__half2*)g_xh;
    o[2 * i]     = __floats2half2_rn(v.x, v.y);
    o[2 * i + 1] = __floats2half2_rn(v.z, v.w);
}

// ---------------- prep: transpose weights -> fp16 [w][N][K] ----------------
__global__ __launch_bounds__(256) void prep_w(const float* __restrict__ kz,
                                              const float* __restrict__ kr,
                                              const float* __restrict__ kh) {
    size_t idx = (size_t)blockIdx.x * 256 + threadIdx.x;
    if (idx >= 3ULL * NN * KK) return;
    int w = (int)(idx / ((size_t)NN * KK));
    size_t rem = idx % ((size_t)NN * KK);
    int n = (int)(rem / KK);
    int k = (int)(rem % KK);
    const float* W = (w == 0) ? kz : (w == 1) ? kr : kh;
    g_wh[idx] = __float2half_rn(W[(size_t)k * NN + n]);
}

// ---------------- mma.sync fp16 GEMM (single term) ----------------
// CTA 128x128, 8 warps (warp_m = wid&3 -> 32 rows, warp_n = wid>>2 -> 64 cols)
// K chunks of 32, 4-stage cp.async pipeline. SMEM row stride 80B (conflict-free).
#define ROWB 80
#define TILE_BYTES (128 * ROWB)                  // 10240
#define STAGE_BYTES (2 * TILE_BYTES)             // A + B = 20480
#define NSTAGE 4
#define GEMM_SMEM (NSTAGE * STAGE_BYTES)         // 81920
#define NCHUNK (KK / 32)                         // 16

__global__ __launch_bounds__(256, 2) void gemm_mma() {
    extern __shared__ char smem[];
    const uint32_t sb = smem_u32(smem);

    const int tid = threadIdx.x;
    const int wid = tid >> 5;
    const int lid = tid & 31;
    const int bn = blockIdx.x * 128;
    const int bm = blockIdx.y * 128;
    const int w  = blockIdx.z;
    const int warp_m = wid & 3;
    const int warp_n = wid >> 2;

    const __half* A = g_xh;
    const __half* B = g_wh + (size_t)w * NN * KK;
    float* Cp = g_proj + (size_t)w * MM * NN;

    const int ldr0 = tid >> 2;            // rows 0..63
    const int ldc  = (tid & 3) * 16;      // byte col
    const int ldq  = (tid & 3) * 8;       // fp16 elem col

    auto load_stage = [&](int chunk, int s) {
        const int k0 = chunk * 32;
        const uint32_t st = sb + s * STAGE_BYTES;
#pragma unroll
        for (int i = 0; i < 2; i++) {
            const int r = ldr0 + i * 64;
            const uint32_t so = (uint32_t)(r * ROWB + ldc);
            CP16(st + so,              A + (size_t)(bm + r) * KK + k0 + ldq);
            CP16(st + TILE_BYTES + so, B + (size_t)(bn + r) * KK + k0 + ldq);
        }
    };

    const int a_r = (lid & 7) + ((lid >> 3) & 1) * 8;
    const int a_c = (lid >> 4) * 16;
    const int b_r = (lid & 7) + ((lid >> 4) ? 8 : 0);
    const int b_c = ((lid >> 3) & 1) * 16;
    const uint32_t aRow = (uint32_t)((warp_m * 32 + a_r) * ROWB + a_c);
    const uint32_t bRow = (uint32_t)((warp_n * 64 + b_r) * ROWB + b_c);

    float acc[2][8][4];
#pragma unroll
    for (int i = 0; i < 2; i++)
#pragma unroll
        for (int j = 0; j < 8; j++)
#pragma unroll
            for (int q = 0; q < 4; q++) acc[i][j][q] = 0.0f;

    load_stage(0, 0); CP_COMMIT();
    load_stage(1, 1); CP_COMMIT();
    load_stage(2, 2); CP_COMMIT();

    for (int c = 0; c < NCHUNK; c++) {
        if (c < NCHUNK - 2)       CP_WAIT(2);
        else if (c == NCHUNK - 2) CP_WAIT(1);
        else                      CP_WAIT(0);
        __syncthreads();
        if (c + 3 < NCHUNK) { load_stage(c + 3, (c + 3) & 3); CP_COMMIT(); }

        const uint32_t st = sb + (c & 3) * STAGE_BYTES;
        const uint32_t aB = st + aRow;
        const uint32_t bB = st + TILE_BYTES + bRow;

#pragma unroll
        for (int kq = 0; kq < 2; kq++) {
            const uint32_t ko = kq * 32;
            uint32_t ah[2][4], bf[8][2];
#pragma unroll
            for (int mt = 0; mt < 2; mt++)
                ldm_x4(aB + mt * (16 * ROWB) + ko, ah[mt][0], ah[mt][1], ah[mt][2], ah[mt][3]);
#pragma unroll
            for (int np = 0; np < 4; np++) {
                uint32_t r0, r1, r2, r3;
                ldm_x4(bB + np * (16 * ROWB) + ko, r0, r1, r2, r3);
                bf[2 * np][0] = r0;     bf[2 * np][1] = r1;
                bf[2 * np + 1][0] = r2; bf[2 * np + 1][1] = r3;
            }
#pragma unroll
            for (int mt = 0; mt < 2; mt++)
#pragma unroll
                for (int nt = 0; nt < 8; nt++)
                    mma_fp16(acc[mt][nt], ah[mt], bf[nt]);
        }
    }

    const int er = lid >> 2;
    const int ec = (lid & 3) * 2;
#pragma unroll
    for (int mt = 0; mt < 2; mt++) {
        const int row = bm + warp_m * 32 + mt * 16 + er;
#pragma unroll
        for (int nt = 0; nt < 8; nt++) {
            const int col = bn + warp_n * 64 + nt * 8 + ec;
            *(float2*)(Cp + (size_t)row * NN + col)       = make_float2(acc[mt][nt][0], acc[mt][nt][1]);
            *(float2*)(Cp + (size_t)(row + 8) * NN + col) = make_float2(acc[mt][nt][2], acc[mt][nt][3]);
        }
    }
}

// ---------------- recurrence scan: float2/thread, depth-8 ring ----------------
__device__ __forceinline__ float brc_step(float xz, float xr, float xh,
                                          float h, float mzv, float mrv,
                                          float bzv, float brv) {
    float r = tanhf(fmaf(h, mrv, xr + brv)) + 1.0f;
    float z = 0.5f * tanhf(0.5f * fmaf(h, mzv, xz + bzv)) + 0.5f;
    float c = tanhf(fmaf(r, h, xh));
    return fmaf(z, h - c, c);
}

#define DEPTH 8

__global__ __launch_bounds__(128) void scan_kernel(
    const float* __restrict__ mz, const float* __restrict__ mr,
    const float* __restrict__ br, const float* __restrict__ bz,
    float* __restrict__ out) {
    const int ch2 = blockIdx.x * blockDim.x + threadIdx.x;   // 0..32767
    const int H2 = HH / 2;
    const int b = ch2 / H2;
    const int h = (ch2 % H2) * 2;

    const float2 mzv = *(const float2*)(mz + h);
    const float2 mrv = *(const float2*)(mr + h);
    const float2 brv = *(const float2*)(br + h);
    const float2 bzv = *(const float2*)(bz + h);

    const size_t base = (size_t)b * TT * HH + h;
    const size_t PLANE = (size_t)MM * NN;
    const float2* pz = (const float2*)(g_proj + 0 * PLANE + base);
    const float2* pr = (const float2*)(g_proj + 1 * PLANE + base);
    const float2* ph = (const float2*)(g_proj + 2 * PLANE + base);
    float2* po = (float2*)(out + base);

    float2 hs = make_float2(0.f, 0.f);
    float2 zb[DEPTH], rb[DEPTH], hb[DEPTH];
#pragma unroll
    for (int s = 0; s < DEPTH; s++) {
        size_t o = (size_t)s * H2;
        zb[s] = pz[o]; rb[s] = pr[o]; hb[s] = ph[o];
    }

#pragma unroll 8
    for (int t = 0; t < TT; t++) {
        const int s = t & (DEPTH - 1);
        float2 xz0 = zb[s], xr0 = rb[s], xh0 = hb[s];
        if (t + DEPTH < TT) {
            size_t o = (size_t)(t + DEPTH) * H2;
            zb[s] = pz[o]; rb[s] = pr[o]; hb[s] = ph[o];
        }
        hs.x = brc_step(xz0.x, xr0.x, xh0.x, hs.x, mzv.x, mrv.x, bzv.x, brv.x);
        hs.y = brc_step(xz0.y, xr0.y, xh0.y, hs.y, mzv.y, mrv.y, bzv.y, brv.y);
        po[(size_t)t * H2] = hs;
    }
}

// ---------------- launch ----------------
extern "C" void kernel_launch(void* const* d_in, const int* in_sizes, int n_in,
                              void* d_out, int out_size) {
    const float* x  = (const float*)d_in[0];
    const float* kz = (const float*)d_in[1];
    const float* kr = (const float*)d_in[2];
    const float* kh = (const float*)d_in[3];
    const float* mz = (const float*)d_in[4];
    const float* mr = (const float*)d_in[5];
    const float* br = (const float*)d_in[6];
    const float* bz = (const float*)d_in[7];
    float* out = (float*)d_out;

    cudaFuncSetAttribute(gemm_mma, cudaFuncAttributeMaxDynamicSharedMemorySize, GEMM_SMEM);

    prep_x<<<(MM * KK / 4 + 255) / 256, 256>>>(x);
    prep_w<<<(3 * NN * KK + 255) / 256, 256>>>(kz, kr, kh);

    dim3 ggrid(NN / 128, MM / 128, 3);   // (8, 256, 3)
    gemm_mma<<<ggrid, 256, GEMM_SMEM>>>();

    scan_kernel<<<(BATCH * HH / 2) / 128, 128>>>(mz, mr, br, bz, out);
}

// round 5
// speedup vs baseline: 5.6743x; 1.2482x over previous
#include <cuda_runtime.h>
#include <cuda_fp16.h>
#include <cstdint>

#define BATCH 64
#define TT    512
#define DD    512
#define HH    1024
#define MM    (BATCH * TT)        // 32768
#define KK    DD                  // 512
#define NN    HH                  // 1024

// ---------------- device scratch (no runtime alloc) ----------------
__device__ float g_proj[3ULL * MM * NN];       // 384 MB fp32 projections
__device__ __half g_xh[(size_t)MM * KK];       // x fp16
__device__ __half g_wh[3ULL * NN * KK];        // weights^T fp16 [w][N][K]

__device__ __forceinline__ uint32_t smem_u32(const void* p) {
    uint32_t a;
    asm("{ .reg .u64 t; cvta.to.shared.u64 t, %1; cvt.u32.u64 %0, t; }" : "=r"(a) : "l"(p));
    return a;
}

#define CP16(sa, gp) asm volatile("cp.async.cg.shared.global [%0], [%1], 16;" :: "r"(sa), "l"(gp))
#define CP_COMMIT()  asm volatile("cp.async.commit_group;" ::: "memory")
#define CP_WAIT(n)   asm volatile("cp.async.wait_group %0;" :: "n"(n) : "memory")

__device__ __forceinline__ void ldm_x4(uint32_t a, uint32_t& r0, uint32_t& r1, uint32_t& r2, uint32_t& r3) {
    asm volatile("ldmatrix.sync.aligned.m8n8.x4.shared.b16 {%0,%1,%2,%3}, [%4];"
                 : "=r"(r0), "=r"(r1), "=r"(r2), "=r"(r3) : "r"(a));
}
__device__ __forceinline__ void mma_fp16(float* d, const uint32_t* a, const uint32_t* b) {
    asm volatile("mma.sync.aligned.m16n8k16.row.col.f32.f16.f16.f32 "
                 "{%0,%1,%2,%3}, {%4,%5,%6,%7}, {%8,%9}, {%0,%1,%2,%3};"
                 : "+f"(d[0]), "+f"(d[1]), "+f"(d[2]), "+f"(d[3])
                 : "r"(a[0]), "r"(a[1]), "r"(a[2]), "r"(a[3]), "r"(b[0]), "r"(b[1]));
}

// ---------------- prep ----------------
__global__ __launch_bounds__(256) void prep_x(const float* __restrict__ x) {
    size_t i = (size_t)blockIdx.x * 256 + threadIdx.x;
    if (i >= (size_t)MM * KK / 4) return;
    float4 v = ((const float4*)x)[i];
    __half2* o = (__half2*)g_xh;
    o[2 * i]     = __floats2half2_rn(v.x, v.y);
    o[2 * i + 1] = __floats2half2_rn(v.z, v.w);
}

__global__ __launch_bounds__(256) void prep_w(const float* __restrict__ kz,
                                              const float* __restrict__ kr,
                                              const float* __restrict__ kh) {
    size_t idx = (size_t)blockIdx.x * 256 + threadIdx.x;
    if (idx >= 3ULL * NN * KK) return;
    int w = (int)(idx / ((size_t)NN * KK));
    size_t rem = idx % ((size_t)NN * KK);
    int n = (int)(rem / KK);
    int k = (int)(rem % KK);
    const float* W = (w == 0) ? kz : (w == 1) ? kr : kh;
    g_wh[idx] = __float2half_rn(W[(size_t)k * NN + n]);
}

// ---------------- mma.sync fp16 GEMM ----------------
// CTA 128x128, 8 warps. K chunks of 64, 3-stage cp.async pipeline.
// SMEM: 128 rows x 64 fp16, row stride 144B (128B data + 16B pad; conflict-free:
// bank(r)=4r mod 32, 8-row ldmatrix sweep covers all banks once).
#define ROWB 144
#define TILE_BYTES (128 * ROWB)                  // 18432
#define STAGE_BYTES (2 * TILE_BYTES)             // 36864
#define NSTAGE 3
#define GEMM_SMEM (NSTAGE * STAGE_BYTES)         // 110592
#define KC 64
#define NCHUNK (KK / KC)                         // 8

__global__ __launch_bounds__(256, 2) void gemm_mma() {
    extern __shared__ char smem[];
    const uint32_t sb = smem_u32(smem);

    const int tid = threadIdx.x;
    const int wid = tid >> 5;
    const int lid = tid & 31;
    const int bn = blockIdx.x * 128;
    const int bm = blockIdx.y * 128;
    const int w  = blockIdx.z;
    const int warp_m = wid & 3;
    const int warp_n = wid >> 2;

    const __half* A = g_xh;
    const __half* B = g_wh + (size_t)w * NN * KK;
    float* Cp = g_proj + (size_t)w * MM * NN;

    // loader: 1024 16B-units per tile, 4 per thread per tile
    auto load_stage = [&](int chunk, int s) {
        const int k0 = chunk * KC;
        const uint32_t st = sb + s * STAGE_BYTES;
#pragma unroll
        for (int i = 0; i < 4; i++) {
            const int u = tid + i * 256;
            const int r = u >> 3;
            const int c16 = u & 7;
            const uint32_t so = (uint32_t)(r * ROWB + c16 * 16);
            CP16(st + so,              A + (size_t)(bm + r) * KK + k0 + c16 * 8);
            CP16(st + TILE_BYTES + so, B + (size_t)(bn + r) * KK + k0 + c16 * 8);
        }
    };

    const int a_r = (lid & 7) + ((lid >> 3) & 1) * 8;
    const int a_c = (lid >> 4) * 16;
    const int b_r = (lid & 7) + ((lid >> 4) ? 8 : 0);
    const int b_c = ((lid >> 3) & 1) * 16;
    const uint32_t aRow = (uint32_t)((warp_m * 32 + a_r) * ROWB + a_c);
    const uint32_t bRow = (uint32_t)((warp_n * 64 + b_r) * ROWB + b_c);

    float acc[2][8][4];
#pragma unroll
    for (int i = 0; i < 2; i++)
#pragma unroll
        for (int j = 0; j < 8; j++)
#pragma unroll
            for (int q = 0; q < 4; q++) acc[i][j][q] = 0.0f;

    load_stage(0, 0); CP_COMMIT();
    load_stage(1, 1); CP_COMMIT();

    for (int c = 0; c < NCHUNK; c++) {
        if (c + 2 < NCHUNK) CP_WAIT(1);
        else                CP_WAIT(0);
        __syncthreads();
        if (c + 2 < NCHUNK) { load_stage(c + 2, (c + 2) % NSTAGE); CP_COMMIT(); }

        const uint32_t st = sb + (c % NSTAGE) * STAGE_BYTES;
        const uint32_t aB = st + aRow;
        const uint32_t bB = st + TILE_BYTES + bRow;

#pragma unroll
        for (int kq = 0; kq < 4; kq++) {          // four k16 steps (byte offsets 0/32/64/96)
            const uint32_t ko = kq * 32;
            uint32_t ah[2][4], bf[8][2];
#pragma unroll
            for (int mt = 0; mt < 2; mt++)
                ldm_x4(aB + mt * (16 * ROWB) + ko, ah[mt][0], ah[mt][1], ah[mt][2], ah[mt][3]);
#pragma unroll
            for (int np = 0; np < 4; np++) {
                uint32_t r0, r1, r2, r3;
                ldm_x4(bB + np * (16 * ROWB) + ko, r0, r1, r2, r3);
                bf[2 * np][0] = r0;     bf[2 * np][1] = r1;
                bf[2 * np + 1][0] = r2; bf[2 * np + 1][1] = r3;
            }
#pragma unroll
            for (int mt = 0; mt < 2; mt++)
#pragma unroll
                for (int nt = 0; nt < 8; nt++)
                    mma_fp16(acc[mt][nt], ah[mt], bf[nt]);
        }
    }

    const int er = lid >> 2;
    const int ec = (lid & 3) * 2;
#pragma unroll
    for (int mt = 0; mt < 2; mt++) {
        const int row = bm + warp_m * 32 + mt * 16 + er;
#pragma unroll
        for (int nt = 0; nt < 8; nt++) {
            const int col = bn + warp_n * 64 + nt * 8 + ec;
            *(float2*)(Cp + (size_t)row * NN + col)       = make_float2(acc[mt][nt][0], acc[mt][nt][1]);
            *(float2*)(Cp + (size_t)(row + 8) * NN + col) = make_float2(acc[mt][nt][2], acc[mt][nt][3]);
        }
    }
}

// ---------------- recurrence scan: 1 channel/thread, MUFU math ----------------
__device__ __forceinline__ float fast_tanh(float x) {
    x = fminf(fmaxf(x, -15.0f), 15.0f);
    float e = __expf(-2.0f * x);              // MUFU.EX2-based, ~2 ulp
    return __fdividef(1.0f - e, 1.0f + e);    // MUFU.RCP-based
}
__device__ __forceinline__ float fast_sigmoid(float x) {
    x = fminf(fmaxf(x, -30.0f), 30.0f);
    return __fdividef(1.0f, 1.0f + __expf(-x));
}
__device__ __forceinline__ float brc_step(float xz, float xr, float xh,
                                          float h, float mzv, float mrv,
                                          float bzv, float brv) {
    float r = fast_tanh(fmaf(h, mrv, xr + brv)) + 1.0f;
    float z = fast_sigmoid(fmaf(h, mzv, xz + bzv));
    float c = fast_tanh(fmaf(r, h, xh));
    return fmaf(z, h - c, c);
}

#define DEPTH 8

__global__ __launch_bounds__(128) void scan_kernel(
    const float* __restrict__ mz, const float* __restrict__ mr,
    const float* __restrict__ br, const float* __restrict__ bz,
    float* __restrict__ out) {
    const int ch = blockIdx.x * blockDim.x + threadIdx.x;   // 0..65535
    const int b = ch >> 10;
    const int h = ch & (HH - 1);

    const float mzv = mz[h], mrv = mr[h], brv = br[h], bzv = bz[h];

    const size_t base = (size_t)b * TT * HH + h;
    const size_t PLANE = (size_t)MM * NN;
    const float* pz = g_proj + 0 * PLANE + base;
    const float* pr = g_proj + 1 * PLANE + base;
    const float* ph = g_proj + 2 * PLANE + base;
    float* po = out + base;

    float hs = 0.0f;
    float zb[DEPTH], rb[DEPTH], hb[DEPTH];
#pragma unroll
    for (int s = 0; s < DEPTH; s++) {
        size_t o = (size_t)s * HH;
        zb[s] = pz[o]; rb[s] = pr[o]; hb[s] = ph[o];
    }

#pragma unroll 8
    for (int t = 0; t < TT; t++) {
        const int s = t & (DEPTH - 1);
        float xz0 = zb[s], xr0 = rb[s], xh0 = hb[s];
        if (t + DEPTH < TT) {
            size_t o = (size_t)(t + DEPTH) * HH;
            zb[s] = pz[o]; rb[s] = pr[o]; hb[s] = ph[o];
        }
        hs = brc_step(xz0, xr0, xh0, hs, mzv, mrv, bzv, brv);
        po[(size_t)t * HH] = hs;
    }
}

// ---------------- launch ----------------
extern "C" void kernel_launch(void* const* d_in, const int* in_sizes, int n_in,
                              void* d_out, int out_size) {
    const float* x  = (const float*)d_in[0];
    const float* kz = (const float*)d_in[1];
    const float* kr = (const float*)d_in[2];
    const float* kh = (const float*)d_in[3];
    const float* mz = (const float*)d_in[4];
    const float* mr = (const float*)d_in[5];
    const float* br = (const float*)d_in[6];
    const float* bz = (const float*)d_in[7];
    float* out = (float*)d_out;

    cudaFuncSetAttribute(gemm_mma, cudaFuncAttributeMaxDynamicSharedMemorySize, GEMM_SMEM);

    prep_x<<<(MM * KK / 4 + 255) / 256, 256>>>(x);
    prep_w<<<(3 * NN * KK + 255) / 256, 256>>>(kz, kr, kh);

    dim3 ggrid(NN / 128, MM / 128, 3);   // (8, 256, 3)
    gemm_mma<<<ggrid, 256, GEMM_SMEM>>>();

    scan_kernel<<<(BATCH * HH) / 128, 128>>>(mz, mr, br, bz, out);
}